// round 11
// baseline (speedup 1.0000x reference)
#include <cuda_runtime.h>

// RX2: apply RX(theta_q) to each of 20 qubits of [16, 2^20] states.
// Stage at global stride 2^k uses qubit 19-k. Packed (re,im) u64 amplitudes,
// f32x2 FMA: 4 fma-pipe instrs per butterfly.
//
// PERSISTENT single-kernel version: one launch, grid = 740 CTAs (all
// resident in wave 1 at 5 CTAs/SM), phase 1 (stages 0..11, contiguous
// 4096-amp tiles) -> one global sense-reversing barrier -> phase 2
// (stages 12..19, 256 strided rows x 16 contiguous), phase 2 walked in
// reverse item order for L2 affinity with phase 1's freshest output.
// No inter-kernel gaps, no tail waves, no streams.

#define NQ   20
#define GRID 740
#define NITEMS 4096              // 16 batches x 256 tiles per phase

typedef unsigned long long u64;

__device__ unsigned g_cnt   = 0;
__device__ unsigned g_sense = 0;

__device__ __forceinline__ u64 pk2(float x, float y) {
    u64 v; asm("mov.b64 %0, {%1, %2};" : "=l"(v) : "f"(x), "f"(y)); return v;
}
__device__ __forceinline__ u64 swp(u64 v) {
    float x, y;
    asm("mov.b64 {%0, %1}, %2;" : "=f"(x), "=f"(y) : "l"(v));
    return pk2(y, x);
}
__device__ __forceinline__ u64 fma2(u64 a, u64 b, u64 c) {
    u64 d; asm("fma.rn.f32x2 %0, %1, %2, %3;" : "=l"(d) : "l"(a), "l"(b), "l"(c)); return d;
}
__device__ __forceinline__ u64 mul2(u64 a, u64 b) {
    u64 d; asm("mul.rn.f32x2 %0, %1, %2;" : "=l"(d) : "l"(a), "l"(b)); return d;
}

// a=(ar,ai), b=(br,bi); c2=(c,c), s2=(s,-s)
// na = c2*a + s2*swap(b) ; nb = c2*b + s2*swap(a)
__device__ __forceinline__ void bfly2(u64& a, u64& b, u64 c2, u64 s2) {
    u64 na = fma2(c2, a, mul2(s2, swp(b)));
    u64 nb = fma2(c2, b, mul2(s2, swp(a)));
    a = na; b = nb;
}

// Sense-reversing global barrier across GRID CTAs. Self-resetting: g_cnt
// returns to 0 and g_sense flips once per launch, so graph replays see a
// clean initial state every time.
__device__ __forceinline__ void grid_barrier() {
    __syncthreads();
    if (threadIdx.x == 0) {
        volatile unsigned* vs = &g_sense;
        unsigned old = *vs;
        __threadfence();                       // phase-1 stores visible first
        unsigned t = atomicAdd(&g_cnt, 1);
        if (t == GRID - 1) {
            atomicExch(&g_cnt, 0);             // reset for next launch
            __threadfence();
            *vs = old ^ 1;                     // release
        } else {
            int d = 8;
            while (*vs == old) { __nanosleep(d); if (d < 256) d += d; }
        }
        __threadfence();                       // acquire
    }
    __syncthreads();
}

// -------------------------------------------------------------------------
// One persistent kernel: coeff tables for all 16 batches in smem, then
// phase-1 loop, global barrier, phase-2 loop.
// -------------------------------------------------------------------------
__global__ __launch_bounds__(256, 5)
void rx_all(const float* __restrict__ phi,
            const float* __restrict__ thetas,
            u64* __restrict__ out)
{
    extern __shared__ u64 sm[];              // 4352 u64 (4096 + pad)
    __shared__ u64 c1[16][12], s1[16][12];   // phase-1 coeffs (stage k, qubit 19-k)
    __shared__ u64 cs0[16];                  // (c0,-s0) for real stage 0
    __shared__ u64 c2t[16][8], s2t[16][8];   // phase-2 coeffs (stage m, qubit 7-m)

    const int t = threadIdx.x;

    // ---- build all coefficient tables once ----
    if (t < 192) {                           // (b, k) for phase 1
        int b = t / 12, k = t - b * 12;
        float sv, cv;
        sincosf(0.5f * thetas[b * NQ + (19 - k)], &sv, &cv);
        c1[b][k] = pk2(cv, cv);
        s1[b][k] = pk2(sv, -sv);
        if (k == 0) cs0[b] = pk2(cv, -sv);
    }
    if (t < 128) {                           // (b, m) for phase 2
        int b = t >> 3, m = t & 7;
        float sv, cv;
        sincosf(0.5f * thetas[b * NQ + (7 - m)], &sv, &cv);
        c2t[b][m] = pk2(cv, cv);
        s2t[b][m] = pk2(sv, -sv);
    }
    __syncthreads();

    // =====================================================================
    // Phase 1: stages 0..11 (qubits 19..8). Item = (b<<8)|tile, tile =
    // 4096 contiguous amps. 3 rounds, 2 smem exchanges; last round fused
    // with coalesced store. Smem pad p = i + (i>>4).
    // =====================================================================
    for (int item = blockIdx.x; item < NITEMS; item += GRID) {
        const int b    = item >> 8;
        const int tile = item & 255;
        const size_t base = ((size_t)b << 20) + ((size_t)tile << 12);

        // issue global loads first
        float rr[16];
        const float4* pin = (const float4*)(phi + base + ((size_t)t << 4));
        #pragma unroll
        for (int q = 0; q < 4; q++) {
            float4 v = __ldcs(pin + q);
            rr[4*q+0] = v.x; rr[4*q+1] = v.y; rr[4*q+2] = v.z; rr[4*q+3] = v.w;
        }

        u64 amp[16];

        // Round A: i = (t<<4)+j ; stages 0..3 (stage 0 on real data)
        {
            const u64 cs = cs0[b];
            #pragma unroll
            for (int j = 0; j < 16; j += 2) {
                amp[j]     = mul2(cs, pk2(rr[j],     rr[j + 1]));
                amp[j + 1] = mul2(cs, pk2(rr[j + 1], rr[j]));
            }
        }
        #pragma unroll
        for (int k = 1; k < 4; k++) {
            const u64 c2 = c1[b][k], s2 = s1[b][k];
            const int m = 1 << k;
            #pragma unroll
            for (int j = 0; j < 16; j++)
                if (!(j & m)) bfly2(amp[j], amp[j | m], c2, s2);
        }
        #pragma unroll
        for (int j = 0; j < 16; j++) {
            int i = (t << 4) + j;
            sm[i + (i >> 4)] = amp[j];
        }
        __syncthreads();

        // Round B: i = (t&15) | (j<<4) | ((t>>4)<<8) ; stages 4..7
        #pragma unroll
        for (int j = 0; j < 16; j++) {
            int i = (t & 15) | (j << 4) | ((t >> 4) << 8);
            amp[j] = sm[i + (i >> 4)];
        }
        #pragma unroll
        for (int k = 4; k < 8; k++) {
            const u64 c2 = c1[b][k], s2 = s1[b][k];
            const int m = 1 << (k - 4);
            #pragma unroll
            for (int j = 0; j < 16; j++)
                if (!(j & m)) bfly2(amp[j], amp[j | m], c2, s2);
        }
        #pragma unroll
        for (int j = 0; j < 16; j++) {       // rewrites exactly what it read
            int i = (t & 15) | (j << 4) | ((t >> 4) << 8);
            sm[i + (i >> 4)] = amp[j];
        }
        __syncthreads();

        // Round C: i = t | (j<<8) ; stages 8..11, fused coalesced store
        #pragma unroll
        for (int j = 0; j < 16; j++) {
            int i = t | (j << 8);
            amp[j] = sm[i + (i >> 4)];
        }
        #pragma unroll
        for (int k = 8; k < 12; k++) {
            const u64 c2 = c1[b][k], s2 = s1[b][k];
            const int m = 1 << (k - 8);
            #pragma unroll
            for (int j = 0; j < 16; j++)
                if (!(j & m)) bfly2(amp[j], amp[j | m], c2, s2);
        }
        {
            u64* po = out + base;
            #pragma unroll
            for (int j = 0; j < 16; j++)     // stays in L2 for phase 2
                po[t | (j << 8)] = amp[j];
        }
        __syncthreads();                     // WAR: next item rewrites sm
    }

    // ===== all phase-1 output visible to every CTA =====
    grid_barrier();

    // =====================================================================
    // Phase 2: stages 12..19 (qubits 7..0), in place. Item = (b<<8)|chunk;
    // tile: h = 0..255 (global bits 12..19) x 16 contiguous (bits 0..3),
    // chunk = global bits 4..11. 2 rounds, ONE smem exchange. Reverse item
    // order: freshest phase-1 output (high b) first while it is L2-hot.
    // =====================================================================
    const int c  = t & 15;
    const int th = t >> 4;                   // 0..15

    for (int it = blockIdx.x; it < NITEMS; it += GRID) {
        const int item  = (NITEMS - 1) - it;
        const int b     = item >> 8;
        const int chunk = item & 255;
        u64* pg = out + ((size_t)b << 20) + ((size_t)chunk << 4);

        // issue global loads first: h = j | (th<<4); 128B segments
        u64 amp[16];
        #pragma unroll
        for (int j = 0; j < 16; j++) {
            int h = j | (th << 4);
            amp[j] = (u64)__ldcs((const long long*)(pg + (((size_t)h << 12) + c)));
        }

        // Round A: stages 0..3 on j = h bits 0..3
        #pragma unroll
        for (int m = 0; m < 4; m++) {
            const u64 c2 = c2t[b][m], s2 = s2t[b][m];
            const int st = 1 << m;
            #pragma unroll
            for (int j = 0; j < 16; j++)
                if (!(j & st)) bfly2(amp[j], amp[j | st], c2, s2);
        }
        #pragma unroll
        for (int j = 0; j < 16; j++) {
            int h = j | (th << 4);
            sm[(h << 4) + c] = amp[j];       // 4096 u64, no pad needed
        }
        __syncthreads();

        // Round B: h = th | (j<<4) ; stages 4..7
        #pragma unroll
        for (int j = 0; j < 16; j++) {
            int h = th | (j << 4);
            amp[j] = sm[(h << 4) + c];
        }
        #pragma unroll
        for (int m = 4; m < 8; m++) {
            const u64 c2 = c2t[b][m], s2 = s2t[b][m];
            const int st = 1 << (m - 4);
            #pragma unroll
            for (int j = 0; j < 16; j++)
                if (!(j & st)) bfly2(amp[j], amp[j | st], c2, s2);
        }
        // final store: streaming (evict-first), coalesced
        #pragma unroll
        for (int j = 0; j < 16; j++) {
            int h = th | (j << 4);
            __stcs((long long*)(pg + (((size_t)h << 12) + c)), (long long)amp[j]);
        }
        __syncthreads();                     // WAR: next item rewrites sm
    }
}

extern "C" void kernel_launch(void* const* d_in, const int* in_sizes, int n_in,
                              void* d_out, int out_size)
{
    const float* phi    = (const float*)d_in[0];   // [16, 2^20] float32
    const float* thetas = (const float*)d_in[1];   // [16, 20]   float32
    u64* out = (u64*)d_out;                        // [16, 2^20] packed (re,im)

    const int SMEM = 4352 * (int)sizeof(u64);      // 34816 B dynamic
    rx_all<<<GRID, 256, SMEM>>>(phi, thetas, out);
}

// round 12
// speedup vs baseline: 1.1425x; 1.1425x over previous
#include <cuda_runtime.h>

// RX2: apply RX(theta_q) to each of 20 qubits of [16, 2^20] states.
// Stage at global stride 2^k uses qubit 19-k. Packed (re,im) u64 amplitudes,
// f32x2 FMA: 4 fma-pipe instrs per butterfly.
//
// PIPELINED PERSISTENT kernel: one launch, 740 CTAs (5/SM, all wave-1
// resident). blockIdx < 384 -> phase-1 workers (stages 0..11, contiguous
// 4096-amp tiles, 3 rounds / 2 smem exchanges), then they fall through to
// phase 2. blockIdx >= 384 -> phase-2 workers (stages 12..19, 256 strided
// rows x 16 contiguous, 2 rounds / 1 exchange), gated per batch by a
// completion counter. Both phases run CONCURRENTLY (heterogeneous mix =
// the overlap that made the 2-stream version fast), with zero launch
// gaps, no wave quantization, and dynamic load balance via atomic queues.

#define NQ     20
#define GRID   740
#define NP1    384               // phase-1 worker CTAs (rest start in p2)
#define NITEMS 4096              // 16 batches x 256 tiles per phase

typedef unsigned long long u64;

__device__ unsigned g_qp1 = 0;          // phase-1 work queue
__device__ unsigned g_qp2 = 0;          // phase-2 work queue
__device__ unsigned g_fin = 0;          // CTA finish counter (for reset)
__device__ unsigned g_done[16] = {};    // per-batch phase-1 completion

__device__ __forceinline__ u64 pk2(float x, float y) {
    u64 v; asm("mov.b64 %0, {%1, %2};" : "=l"(v) : "f"(x), "f"(y)); return v;
}
__device__ __forceinline__ u64 swp(u64 v) {
    float x, y;
    asm("mov.b64 {%0, %1}, %2;" : "=f"(x), "=f"(y) : "l"(v));
    return pk2(y, x);
}
__device__ __forceinline__ u64 fma2(u64 a, u64 b, u64 c) {
    u64 d; asm("fma.rn.f32x2 %0, %1, %2, %3;" : "=l"(d) : "l"(a), "l"(b), "l"(c)); return d;
}
__device__ __forceinline__ u64 mul2(u64 a, u64 b) {
    u64 d; asm("mul.rn.f32x2 %0, %1, %2;" : "=l"(d) : "l"(a), "l"(b)); return d;
}

// a=(ar,ai), b=(br,bi); c2=(c,c), s2=(s,-s)
// na = c2*a + s2*swap(b) ; nb = c2*b + s2*swap(a)
__device__ __forceinline__ void bfly2(u64& a, u64& b, u64 c2, u64 s2) {
    u64 na = fma2(c2, a, mul2(s2, swp(b)));
    u64 nb = fma2(c2, b, mul2(s2, swp(a)));
    a = na; b = nb;
}

__global__ __launch_bounds__(256, 5)
void rx_all(const float* __restrict__ phi,
            const float* __restrict__ thetas,
            u64* __restrict__ out)
{
    extern __shared__ u64 sm[];              // 4352 u64 (4096 + pad)
    __shared__ u64 c1[16][12], s1[16][12];   // phase-1 coeffs (stage k -> qubit 19-k)
    __shared__ u64 cs0[16];                  // (c0,-s0) for real stage 0
    __shared__ u64 c2t[16][8], s2t[16][8];   // phase-2 coeffs (stage m -> qubit 7-m)
    __shared__ unsigned s_item;

    const int t = threadIdx.x;

    // ---- coefficient tables for all 16 batches ----
    if (t < 192) {
        int b = t / 12, k = t - b * 12;
        float sv, cv;
        sincosf(0.5f * thetas[b * NQ + (19 - k)], &sv, &cv);
        c1[b][k] = pk2(cv, cv);
        s1[b][k] = pk2(sv, -sv);
        if (k == 0) cs0[b] = pk2(cv, -sv);
    }
    if (t < 128) {
        int b = t >> 3, m = t & 7;
        float sv, cv;
        sincosf(0.5f * thetas[b * NQ + (7 - m)], &sv, &cv);
        c2t[b][m] = pk2(cv, cv);
        s2t[b][m] = pk2(sv, -sv);
    }
    __syncthreads();

    // =====================================================================
    // Phase 1 workers: stages 0..11, tile = 4096 contiguous amps.
    // Items claimed from g_qp1 (batch-major -> batches complete in order).
    // =====================================================================
    if (blockIdx.x < NP1) {
        for (;;) {
            if (t == 0) s_item = atomicAdd(&g_qp1, 1);
            __syncthreads();
            const unsigned item = s_item;
            if (item >= NITEMS) break;

            const int b    = item >> 8;
            const int tile = item & 255;
            const size_t base = ((size_t)b << 20) + ((size_t)tile << 12);

            // issue global loads first
            float rr[16];
            const float4* pin = (const float4*)(phi + base + ((size_t)t << 4));
            #pragma unroll
            for (int q = 0; q < 4; q++) {
                float4 v = __ldcs(pin + q);
                rr[4*q+0] = v.x; rr[4*q+1] = v.y; rr[4*q+2] = v.z; rr[4*q+3] = v.w;
            }

            u64 amp[16];

            // Round A: i = (t<<4)+j ; stages 0..3 (stage 0 on real data)
            {
                const u64 cs = cs0[b];
                #pragma unroll
                for (int j = 0; j < 16; j += 2) {
                    amp[j]     = mul2(cs, pk2(rr[j],     rr[j + 1]));
                    amp[j + 1] = mul2(cs, pk2(rr[j + 1], rr[j]));
                }
            }
            #pragma unroll
            for (int k = 1; k < 4; k++) {
                const u64 c2 = c1[b][k], s2 = s1[b][k];
                const int m = 1 << k;
                #pragma unroll
                for (int j = 0; j < 16; j++)
                    if (!(j & m)) bfly2(amp[j], amp[j | m], c2, s2);
            }
            #pragma unroll
            for (int j = 0; j < 16; j++) {
                int i = (t << 4) + j;
                sm[i + (i >> 4)] = amp[j];
            }
            __syncthreads();

            // Round B: i = (t&15) | (j<<4) | ((t>>4)<<8) ; stages 4..7
            #pragma unroll
            for (int j = 0; j < 16; j++) {
                int i = (t & 15) | (j << 4) | ((t >> 4) << 8);
                amp[j] = sm[i + (i >> 4)];
            }
            #pragma unroll
            for (int k = 4; k < 8; k++) {
                const u64 c2 = c1[b][k], s2 = s1[b][k];
                const int m = 1 << (k - 4);
                #pragma unroll
                for (int j = 0; j < 16; j++)
                    if (!(j & m)) bfly2(amp[j], amp[j | m], c2, s2);
            }
            #pragma unroll
            for (int j = 0; j < 16; j++) {   // rewrites exactly what it read
                int i = (t & 15) | (j << 4) | ((t >> 4) << 8);
                sm[i + (i >> 4)] = amp[j];
            }
            __syncthreads();

            // Round C: i = t | (j<<8) ; stages 8..11, fused coalesced store
            #pragma unroll
            for (int j = 0; j < 16; j++) {
                int i = t | (j << 8);
                amp[j] = sm[i + (i >> 4)];
            }
            #pragma unroll
            for (int k = 8; k < 12; k++) {
                const u64 c2 = c1[b][k], s2 = s1[b][k];
                const int m = 1 << (k - 8);
                #pragma unroll
                for (int j = 0; j < 16; j++)
                    if (!(j & m)) bfly2(amp[j], amp[j | m], c2, s2);
            }
            {
                u64* po = out + base;
                #pragma unroll
                for (int j = 0; j < 16; j++) // stays in L2 for phase 2
                    po[t | (j << 8)] = amp[j];
            }

            // publish completion: stores visible device-wide, then count
            __threadfence();
            __syncthreads();                 // also protects sm for next item
            if (t == 0) atomicAdd(&g_done[b], 1);
        }
    }

    // =====================================================================
    // Phase 2 (all CTAs end up here): stages 12..19, in place.
    // Tile: h = 0..255 (global bits 12..19) x 16 contiguous (bits 0..3);
    // chunk = global bits 4..11. Gated on g_done[b] == 256.
    // =====================================================================
    const int c  = t & 15;
    const int th = t >> 4;                   // 0..15

    for (;;) {
        if (t == 0) s_item = atomicAdd(&g_qp2, 1);
        __syncthreads();
        const unsigned item = s_item;
        if (item >= NITEMS) break;

        const int b     = item >> 8;
        const int chunk = item & 255;

        // wait until all 256 phase-1 tiles of batch b have been published
        if (t == 0) {
            volatile unsigned* vd = &g_done[b];
            int d = 32;
            while (*vd < 256u) { __nanosleep(d); if (d < 512) d += d; }
            __threadfence();                 // acquire
        }
        __syncthreads();

        u64* pg = out + ((size_t)b << 20) + ((size_t)chunk << 4);

        // loads: h = j | (th<<4); 128B segments, L2-coherent (.cg)
        u64 amp[16];
        #pragma unroll
        for (int j = 0; j < 16; j++) {
            int h = j | (th << 4);
            amp[j] = (u64)__ldcg((const long long*)(pg + (((size_t)h << 12) + c)));
        }

        // Round A: stages 0..3 on j = h bits 0..3
        #pragma unroll
        for (int m = 0; m < 4; m++) {
            const u64 c2 = c2t[b][m], s2 = s2t[b][m];
            const int st = 1 << m;
            #pragma unroll
            for (int j = 0; j < 16; j++)
                if (!(j & st)) bfly2(amp[j], amp[j | st], c2, s2);
        }
        #pragma unroll
        for (int j = 0; j < 16; j++) {
            int h = j | (th << 4);
            sm[(h << 4) + c] = amp[j];       // 4096 u64 region, conflict-free
        }
        __syncthreads();

        // Round B: h = th | (j<<4) ; stages 4..7
        #pragma unroll
        for (int j = 0; j < 16; j++) {
            int h = th | (j << 4);
            amp[j] = sm[(h << 4) + c];
        }
        #pragma unroll
        for (int m = 4; m < 8; m++) {
            const u64 c2 = c2t[b][m], s2 = s2t[b][m];
            const int st = 1 << (m - 4);
            #pragma unroll
            for (int j = 0; j < 16; j++)
                if (!(j & st)) bfly2(amp[j], amp[j | st], c2, s2);
        }
        // final store: streaming (evict-first), coalesced
        #pragma unroll
        for (int j = 0; j < 16; j++) {
            int h = th | (j << 4);
            __stcs((long long*)(pg + (((size_t)h << 12) + c)), (long long)amp[j]);
        }
        __syncthreads();                     // WAR: next item rewrites sm
    }

    // ---- last CTA to finish resets all global state for the next replay ----
    if (t == 0) {
        unsigned r = atomicAdd(&g_fin, 1);
        if (r == GRID - 1) {
            g_qp1 = 0; g_qp2 = 0; g_fin = 0;
            #pragma unroll
            for (int b = 0; b < 16; b++) g_done[b] = 0;
            __threadfence();
        }
    }
}

extern "C" void kernel_launch(void* const* d_in, const int* in_sizes, int n_in,
                              void* d_out, int out_size)
{
    const float* phi    = (const float*)d_in[0];   // [16, 2^20] float32
    const float* thetas = (const float*)d_in[1];   // [16, 20]   float32
    u64* out = (u64*)d_out;                        // [16, 2^20] packed (re,im)

    const int SMEM = 4352 * (int)sizeof(u64);      // 34816 B dynamic
    rx_all<<<GRID, 256, SMEM>>>(phi, thetas, out);
}

// round 13
// speedup vs baseline: 1.4388x; 1.2594x over previous
#include <cuda_runtime.h>

// RX2: apply RX(theta_q) to each of 20 qubits of [16, 2^20] states.
// Stage at global stride 2^k uses qubit 19-k. Packed (re,im) u64 amplitudes,
// f32x2 FMA: 4 fma-pipe instrs per butterfly.
//
// R10 kernel bodies (best known: 256 threads, 16 amps/thread, 4096-amp
// tiles, 5 CTAs/SM), with THREE concurrency lanes: the capturing legacy
// stream plus 2 forked worker streams. 8 groups of 2 batches round-robin
// over the lanes; each lane serializes p1(g)->p2(g), lanes overlap.
// 512-CTA kernels are deliberately sub-resident so three lanes' CTAs
// interleave on the SMs (heterogeneous p1/p2 mix fills stall slots).

#define NQ 20
typedef unsigned long long u64;

__device__ __forceinline__ u64 pk2(float x, float y) {
    u64 v; asm("mov.b64 %0, {%1, %2};" : "=l"(v) : "f"(x), "f"(y)); return v;
}
__device__ __forceinline__ u64 swp(u64 v) {
    float x, y;
    asm("mov.b64 {%0, %1}, %2;" : "=f"(x), "=f"(y) : "l"(v));
    return pk2(y, x);
}
__device__ __forceinline__ u64 fma2(u64 a, u64 b, u64 c) {
    u64 d; asm("fma.rn.f32x2 %0, %1, %2, %3;" : "=l"(d) : "l"(a), "l"(b), "l"(c)); return d;
}
__device__ __forceinline__ u64 mul2(u64 a, u64 b) {
    u64 d; asm("mul.rn.f32x2 %0, %1, %2;" : "=l"(d) : "l"(a), "l"(b)); return d;
}

// a=(ar,ai), b=(br,bi); c2=(c,c), s2=(s,-s)
// na = c2*a + s2*swap(b) ; nb = c2*b + s2*swap(a)
__device__ __forceinline__ void bfly2(u64& a, u64& b, u64 c2, u64 s2) {
    u64 na = fma2(c2, a, mul2(s2, swp(b)));
    u64 nb = fma2(c2, b, mul2(s2, swp(a)));
    a = na; b = nb;
}

// -------------------------------------------------------------------------
// Pass 1: stages 0..11 (qubits 19..8). Tile = 4096 contiguous amplitudes.
// 256 threads, 16 amps/thread. Rounds: stages 0-3 / 4-7 / 8-11; the last
// round is fused with a fully-coalesced global store.
// Smem pad p = i + (i>>4): all phases conflict-free.
// -------------------------------------------------------------------------
__global__ __launch_bounds__(256, 5)
void rx_pass1(const float* __restrict__ phi,
              const float* __restrict__ thetas,
              u64* __restrict__ out, int b0)
{
    extern __shared__ u64 sm[];              // 4352 u64 (4096 + pad)
    __shared__ u64 c2B[12], s2B[12];
    __shared__ u64 cs0;                      // (c0, -s0) for real stage 0

    const int t    = threadIdx.x;            // 0..255
    const int b    = b0 + blockIdx.y;
    const int tile = blockIdx.x;
    const size_t base = ((size_t)b << 20) + ((size_t)tile << 12);

    // ---- issue global loads first (overlap with coeff sincos + barrier) ----
    float rr[16];
    const float4* pin = (const float4*)(phi + base + ((size_t)t << 4));
    #pragma unroll
    for (int q = 0; q < 4; q++) {
        float4 v = __ldcs(pin + q);
        rr[4*q+0] = v.x; rr[4*q+1] = v.y; rr[4*q+2] = v.z; rr[4*q+3] = v.w;
    }

    if (t < 12) {
        float sv, cv;
        sincosf(0.5f * thetas[b * NQ + (19 - t)], &sv, &cv);
        c2B[t] = pk2(cv, cv);
        s2B[t] = pk2(sv, -sv);
        if (t == 0) cs0 = pk2(cv, -sv);
    }
    __syncthreads();   // coeffs visible

    u64 amp[16];

    // ---- Round A: i = (t<<4)+j ; stages 0..3 (stage 0 on real data) ----
    {
        const u64 cs = cs0;
        #pragma unroll
        for (int j = 0; j < 16; j += 2) {
            // na = (c*ar, -s*br), nb = (c*br, -s*ar)
            amp[j]     = mul2(cs, pk2(rr[j],     rr[j + 1]));
            amp[j + 1] = mul2(cs, pk2(rr[j + 1], rr[j]));
        }
    }
    #pragma unroll
    for (int k = 1; k < 4; k++) {
        const u64 c2 = c2B[k], s2 = s2B[k];
        const int m = 1 << k;
        #pragma unroll
        for (int j = 0; j < 16; j++)
            if (!(j & m)) bfly2(amp[j], amp[j | m], c2, s2);
    }
    #pragma unroll
    for (int j = 0; j < 16; j++) {
        int i = (t << 4) + j;
        sm[i + (i >> 4)] = amp[j];
    }
    __syncthreads();

    // ---- Round B: i = (t&15) | (j<<4) | ((t>>4)<<8) ; stages 4..7 ----
    #pragma unroll
    for (int j = 0; j < 16; j++) {
        int i = (t & 15) | (j << 4) | ((t >> 4) << 8);
        amp[j] = sm[i + (i >> 4)];
    }
    #pragma unroll
    for (int k = 4; k < 8; k++) {
        const u64 c2 = c2B[k], s2 = s2B[k];
        const int m = 1 << (k - 4);
        #pragma unroll
        for (int j = 0; j < 16; j++)
            if (!(j & m)) bfly2(amp[j], amp[j | m], c2, s2);
    }
    #pragma unroll
    for (int j = 0; j < 16; j++) {           // rewrites exactly what it read
        int i = (t & 15) | (j << 4) | ((t >> 4) << 8);
        sm[i + (i >> 4)] = amp[j];
    }
    __syncthreads();

    // ---- Round C: i = t | (j<<8) ; stages 8..11, fused coalesced store ----
    #pragma unroll
    for (int j = 0; j < 16; j++) {
        int i = t | (j << 8);
        amp[j] = sm[i + (i >> 4)];
    }
    #pragma unroll
    for (int k = 8; k < 12; k++) {
        const u64 c2 = c2B[k], s2 = s2B[k];
        const int m = 1 << (k - 8);
        #pragma unroll
        for (int j = 0; j < 16; j++)
            if (!(j & m)) bfly2(amp[j], amp[j | m], c2, s2);
    }
    {
        u64* po = out + base;
        #pragma unroll
        for (int j = 0; j < 16; j++)         // stays in L2 for pass2
            po[t | (j << 8)] = amp[j];
    }
}

// -------------------------------------------------------------------------
// Pass 2: stages 12..19 (qubits 7..0), in place on out.
// Tile: h = 0..255 (global bits 12..19, stride 4096) x 16 contiguous
// (bits 0..3); chunk = global bits 4..11. 256 threads, 16 amps/thread,
// ONE smem exchange. c = t&15 rides the lanes: 128B-per-row coalescing,
// conflict-free smem.
//   Round A: j = h bits 0..3 (stages 0..3)
//   Round B: j = h bits 4..7 (stages 4..7)
// -------------------------------------------------------------------------
__global__ __launch_bounds__(256, 5)
void rx_pass2(const float* __restrict__ thetas,
              u64* __restrict__ out, int b0)
{
    extern __shared__ u64 sm2[];             // 4096 u64
    __shared__ u64 c2B[8], s2B[8];

    const int t     = threadIdx.x;           // 0..255
    const int b     = b0 + blockIdx.y;
    const int chunk = blockIdx.x;            // global bits 4..11

    u64* pg = out + ((size_t)b << 20) + ((size_t)chunk << 4);
    const int c  = t & 15;
    const int th = t >> 4;                   // 0..15

    // ---- issue global loads first: h = j | (th<<4) ----
    u64 amp[16];
    #pragma unroll
    for (int j = 0; j < 16; j++) {
        int h = j | (th << 4);
        amp[j] = (u64)__ldcs((const long long*)(pg + (((size_t)h << 12) + c)));
    }

    if (t < 8) {
        // stage m: global stride 2^(12+m) -> qubit 7-m
        float sv, cv;
        sincosf(0.5f * thetas[b * NQ + (7 - t)], &sv, &cv);
        c2B[t] = pk2(cv, cv);
        s2B[t] = pk2(sv, -sv);
    }
    __syncthreads();   // coeffs visible

    // ---- Round A: stages 0..3 on j = h bits 0..3 ----
    #pragma unroll
    for (int m = 0; m < 4; m++) {
        const u64 c2 = c2B[m], s2 = s2B[m];
        const int st = 1 << m;
        #pragma unroll
        for (int j = 0; j < 16; j++)
            if (!(j & st)) bfly2(amp[j], amp[j | st], c2, s2);
    }
    #pragma unroll
    for (int j = 0; j < 16; j++) {
        int h = j | (th << 4);
        sm2[(h << 4) + c] = amp[j];
    }
    __syncthreads();

    // ---- Round B: h = th | (j<<4) ; stages 4..7 ----
    #pragma unroll
    for (int j = 0; j < 16; j++) {
        int h = th | (j << 4);
        amp[j] = sm2[(h << 4) + c];
    }
    #pragma unroll
    for (int m = 4; m < 8; m++) {
        const u64 c2 = c2B[m], s2 = s2B[m];
        const int st = 1 << (m - 4);
        #pragma unroll
        for (int j = 0; j < 16; j++)
            if (!(j & st)) bfly2(amp[j], amp[j | st], c2, s2);
    }
    // ---- final store: streaming (evict-first), coalesced ----
    #pragma unroll
    for (int j = 0; j < 16; j++) {
        int h = th | (j << 4);
        __stcs((long long*)(pg + (((size_t)h << 12) + c)), (long long)amp[j]);
    }
}

extern "C" void kernel_launch(void* const* d_in, const int* in_sizes, int n_in,
                              void* d_out, int out_size)
{
    const float* phi    = (const float*)d_in[0];   // [16, 2^20] float32
    const float* thetas = (const float*)d_in[1];   // [16, 20]   float32
    u64* out = (u64*)d_out;                        // [16, 2^20] packed (re,im)

    const int SM1 = 4352 * (int)sizeof(u64);       // 34816 B
    const int SM2 = 4096 * (int)sizeof(u64);       // 32768 B
    cudaFuncSetAttribute(rx_pass1, cudaFuncAttributeMaxDynamicSharedMemorySize, SM1);
    cudaFuncSetAttribute(rx_pass2, cudaFuncAttributeMaxDynamicSharedMemorySize, SM2);

    // Host-side stream/event resources: EXACT round-7 config (2 streams,
    // 3 events) — proven teardown-clean. No new objects (R8 showed stream
    // #3+ lazily allocates a 2MB pool that fails the teardown check).
    static cudaStream_t s[2] = {nullptr, nullptr};
    static cudaEvent_t eRoot = nullptr, eDone[2] = {nullptr, nullptr};
    if (!s[0]) {
        cudaStreamCreateWithFlags(&s[0], cudaStreamNonBlocking);
        cudaStreamCreateWithFlags(&s[1], cudaStreamNonBlocking);
        cudaEventCreateWithFlags(&eRoot,    cudaEventDisableTiming);
        cudaEventCreateWithFlags(&eDone[0], cudaEventDisableTiming);
        cudaEventCreateWithFlags(&eDone[1], cudaEventDisableTiming);
    }

    // Fork the two worker streams off the (capturing) legacy stream. The
    // legacy stream itself is the third lane: kernels launched on it after
    // the fork form a parallel branch in the captured graph.
    cudaEventRecord(eRoot, 0);
    cudaStreamWaitEvent(s[0], eRoot, 0);
    cudaStreamWaitEvent(s[1], eRoot, 0);

    // 8 groups of 2 batches over 3 lanes {legacy, s0, s1}.
    for (int g = 0; g < 8; g++) {
        int lane = g % 3;
        cudaStream_t st = (lane == 0) ? (cudaStream_t)0 : s[lane - 1];
        dim3 grid(256, 2);
        rx_pass1<<<grid, 256, SM1, st>>>(phi, thetas, out, g * 2);
        rx_pass2<<<grid, 256, SM2, st>>>(thetas, out, g * 2);
    }

    // Join the worker streams back into the legacy stream (its own lane's
    // kernels are already ordered before this point in-stream).
    cudaEventRecord(eDone[0], s[0]);
    cudaEventRecord(eDone[1], s[1]);
    cudaStreamWaitEvent(0, eDone[0], 0);
    cudaStreamWaitEvent(0, eDone[1], 0);
}